// round 12
// baseline (speedup 1.0000x reference)
#include <cuda_runtime.h>
#include <cstdint>

#define NB 8      // batch
#define NP 3249   // grid points
#define NS 128    // axon segments
#define NE 60     // electrodes
#define NWARPS 7
#define THREADS (NWARPS * 32)          // 224
#define NBLOCKS 148
#define TILE_FLOATS (NS * NE)          // 7680
#define TILE_BYTES (TILE_FLOATS * 4)   // 30720
#define NSTREAMS (NBLOCKS * NWARPS)    // 1036 (prologue points 0..1035)

#define SMEM_BYTES (NWARPS * TILE_BYTES + NE * NB * 4 + NWARPS * 8 + 64)

__device__ int g_ticket;

__global__ void ticket_init_kernel() { g_ticket = NSTREAMS; }

__device__ __forceinline__ unsigned long long dup2(float x) {
    unsigned long long r;
    asm("mov.b64 %0, {%1, %1};" : "=l"(r) : "f"(x));
    return r;
}
__device__ __forceinline__ void fma2(unsigned long long& d,
                                     unsigned long long a,
                                     unsigned long long b) {
    asm("fma.rn.f32x2 %0, %1, %2, %0;" : "+l"(d) : "l"(a), "l"(b));
}

__device__ __forceinline__ void mbar_wait(uint32_t addr, uint32_t parity) {
    uint32_t done;
    asm volatile("{\n\t.reg .pred p;\n\t"
                 "mbarrier.try_wait.parity.acquire.cta.shared::cta.b64 p, [%1], %2;\n\t"
                 "selp.b32 %0, 1, 0, p;\n\t}"
                 : "=r"(done) : "r"(addr), "r"(parity) : "memory");
    while (!done) {
        asm volatile("{\n\t.reg .pred p;\n\t"
                     "mbarrier.try_wait.parity.acquire.cta.shared::cta.b64 p, [%1], %2, 0x989680;\n\t"
                     "selp.b32 %0, 1, 0, p;\n\t}"
                     : "=r"(done) : "r"(addr), "r"(parity) : "memory");
    }
}

__device__ __forceinline__ void tma_fill(uint32_t tile_addr, uint32_t mbar_addr,
                                         const float* src) {
    asm volatile("mbarrier.arrive.expect_tx.shared.b64 _, [%0], %1;"
                 :: "r"(mbar_addr), "r"((uint32_t)TILE_BYTES) : "memory");
    asm volatile("cp.async.bulk.shared::cluster.global.mbarrier::complete_tx::bytes "
                 "[%0], [%1], %2, [%3];"
                 :: "r"(tile_addr), "l"(src), "r"((uint32_t)TILE_BYTES), "r"(mbar_addr)
                 : "memory");
}

// Persistent: 148 blocks x 224 threads (7 warps). Each warp owns ONE private
// tile stage + mbarrier (waiter == refiller: race-free parity), computes a
// whole point (4 rows/thread -> minimal amp broadcast LDS), argmax via pure
// warp shuffles. NEW: points beyond the first 1036 are claimed dynamically
// from a global atomic ticket, eliminating the static-stride quantization
// tail (previously a 4th wave with only 141/1036 warps active).
__global__ __launch_bounds__(THREADS, 1)
void axon_map_kernel(const float* __restrict__ amp,
                     const float* __restrict__ pexp,
                     float* __restrict__ out) {
    extern __shared__ __align__(128) char smem_raw[];
    float* tiles = reinterpret_cast<float*>(smem_raw);              // [NWARPS][7680]
    float* ampt  = tiles + NWARPS * TILE_FLOATS;                    // [NE][NB]
    unsigned long long* mbar =
        reinterpret_cast<unsigned long long*>(ampt + NE * NB);      // [NWARPS]

    const int tid  = threadIdx.x;
    const int warp = tid >> 5;
    const int lane = tid & 31;
    const int bid  = blockIdx.x;

    const uint32_t my_tile_addr =
        (uint32_t)__cvta_generic_to_shared(tiles + warp * TILE_FLOATS);
    const uint32_t my_mbar_addr =
        (uint32_t)__cvta_generic_to_shared(&mbar[warp]);

    if (tid < NWARPS) {
        const uint32_t a = (uint32_t)__cvta_generic_to_shared(&mbar[tid]);
        asm volatile("mbarrier.init.shared.b64 [%0], 1;" :: "r"(a) : "memory");
    }
    for (int i = tid; i < NB * NE; i += THREADS) {
        const int b = i / NE, e = i % NE;
        ampt[e * NB + b] = amp[i];
    }
    __syncthreads();

    const float* tile = tiles + warp * TILE_FLOATS;

    // Prologue: stream s = bid*NWARPS+warp starts on point s (< 1036 < NP).
    int p = bid * NWARPS + warp;
    if (lane == 0)
        tma_fill(my_tile_addr, my_mbar_addr, pexp + (size_t)p * TILE_FLOATS);

    uint32_t parity = 0;
    while (p < NP) {
        mbar_wait(my_mbar_addr, parity);
        parity ^= 1u;

        unsigned long long acc[4][4];   // [row r][batch pair q]
        #pragma unroll
        for (int r = 0; r < 4; r++)
            #pragma unroll
            for (int q = 0; q < 4; q++) acc[r][q] = 0ull;

        #pragma unroll
        for (int j = 0; j < NE / 4; j++) {
            float4 pe[4];
            #pragma unroll
            for (int r = 0; r < 4; r++)
                pe[r] = *reinterpret_cast<const float4*>(tile + (lane + 32 * r) * NE + 4 * j);
            #pragma unroll
            for (int k = 0; k < 4; k++) {
                const int e = 4 * j + k;
                const ulonglong2 alo = *reinterpret_cast<const ulonglong2*>(ampt + e * NB);
                const ulonglong2 ahi = *reinterpret_cast<const ulonglong2*>(ampt + e * NB + 4);
                #pragma unroll
                for (int r = 0; r < 4; r++) {
                    const float pv = (k == 0) ? pe[r].x : (k == 1) ? pe[r].y
                                   : (k == 2) ? pe[r].z : pe[r].w;
                    const unsigned long long d = dup2(pv);
                    fma2(acc[r][0], d, alo.x);
                    fma2(acc[r][1], d, alo.y);
                    fma2(acc[r][2], d, ahi.x);
                    fma2(acc[r][3], d, ahi.y);
                }
            }
        }

        // Claim the next point dynamically and refill own stage for it.
        // Fence orders our generic-proxy tile reads before the async-proxy
        // TMA write; the fill then overlaps the argmax reduction below.
        int pn;
        if (lane == 0) pn = atomicAdd(&g_ticket, 1);
        pn = __shfl_sync(0xffffffffu, pn, 0);
        if (pn < NP) {
            asm volatile("fence.proxy.async.shared::cta;" ::: "memory");
            __syncwarp();
            if (lane == 0)
                tma_fill(my_tile_addr, my_mbar_addr,
                         pexp + (size_t)pn * TILE_FLOATS);
        }

        // abs-argmax over 128 segments per batch: 4-way local, 5-step shuffle.
        #pragma unroll
        for (int b = 0; b < NB; b++) {
            const int q = b >> 1;
            float bv = 0.0f, ba = -1.0f;
            #pragma unroll
            for (int r = 0; r < 4; r++) {
                const unsigned long long pa = acc[r][q];
                const float v = __uint_as_float((b & 1) ? (uint32_t)(pa >> 32) : (uint32_t)pa);
                const float a = fabsf(v);
                if (a > ba) { ba = a; bv = v; }
            }
            #pragma unroll
            for (int off = 16; off > 0; off >>= 1) {
                const float oa = __shfl_xor_sync(0xffffffffu, ba, off);
                const float ov = __shfl_xor_sync(0xffffffffu, bv, off);
                if (oa > ba) { ba = oa; bv = ov; }
            }
            if (lane == 0) out[b * NP + p] = bv;   // threshold |v|>0 is identity
        }

        p = pn;
    }
}

extern "C" void kernel_launch(void* const* d_in, const int* in_sizes, int n_in,
                              void* d_out, int out_size) {
    (void)n_in; (void)out_size;
    const float* a0 = (const float*)d_in[0];
    const float* a1 = (const float*)d_in[1];
    const float* amp  = a0;
    const float* pexp = a1;
    if (in_sizes[0] != NB * NE) { amp = a1; pexp = a0; }

    cudaFuncSetAttribute(axon_map_kernel,
                         cudaFuncAttributeMaxDynamicSharedMemorySize, SMEM_BYTES);
    ticket_init_kernel<<<1, 1>>>();
    axon_map_kernel<<<NBLOCKS, THREADS, SMEM_BYTES>>>(amp, pexp, (float*)d_out);
}

// round 14
// speedup vs baseline: 1.0016x; 1.0016x over previous
#include <cuda_runtime.h>
#include <cstdint>

#define NB 8      // batch
#define NP 3249   // grid points
#define NS 128    // axon segments
#define NE 60     // electrodes
#define NWARPS 7
#define THREADS (NWARPS * 32)          // 224
#define NBLOCKS 148
#define TILE_FLOATS (NS * NE)          // 7680
#define TILE_BYTES (TILE_FLOATS * 4)   // 30720
#define NSTREAMS (NBLOCKS * NWARPS)    // 1036 (prologue points 0..1035)

#define SMEM_BYTES (NWARPS * TILE_BYTES + NE * NB * 4 + NWARPS * 8 + 64)

// Work-stealing ticket. Self-resetting: every launch claims exactly NP
// tickets (one per processed point), and the last stream to finish restores
// g_ticket/g_done for the next (graph-replayed) launch. Static initializers
// provide the correct state for the very first run.
__device__ int g_ticket = NSTREAMS;
__device__ int g_done = 0;

__device__ __forceinline__ unsigned long long dup2(float x) {
    unsigned long long r;
    asm("mov.b64 %0, {%1, %1};" : "=l"(r) : "f"(x));
    return r;
}
__device__ __forceinline__ void fma2(unsigned long long& d,
                                     unsigned long long a,
                                     unsigned long long b) {
    asm("fma.rn.f32x2 %0, %1, %2, %0;" : "+l"(d) : "l"(a), "l"(b));
}

__device__ __forceinline__ void mbar_wait(uint32_t addr, uint32_t parity) {
    uint32_t done;
    asm volatile("{\n\t.reg .pred p;\n\t"
                 "mbarrier.try_wait.parity.acquire.cta.shared::cta.b64 p, [%1], %2;\n\t"
                 "selp.b32 %0, 1, 0, p;\n\t}"
                 : "=r"(done) : "r"(addr), "r"(parity) : "memory");
    while (!done) {
        asm volatile("{\n\t.reg .pred p;\n\t"
                     "mbarrier.try_wait.parity.acquire.cta.shared::cta.b64 p, [%1], %2, 0x989680;\n\t"
                     "selp.b32 %0, 1, 0, p;\n\t}"
                     : "=r"(done) : "r"(addr), "r"(parity) : "memory");
    }
}

__device__ __forceinline__ void tma_fill(uint32_t tile_addr, uint32_t mbar_addr,
                                         const float* src) {
    asm volatile("mbarrier.arrive.expect_tx.shared.b64 _, [%0], %1;"
                 :: "r"(mbar_addr), "r"((uint32_t)TILE_BYTES) : "memory");
    asm volatile("cp.async.bulk.shared::cluster.global.mbarrier::complete_tx::bytes "
                 "[%0], [%1], %2, [%3];"
                 :: "r"(tile_addr), "l"(src), "r"((uint32_t)TILE_BYTES), "r"(mbar_addr)
                 : "memory");
}

// Persistent: 148 blocks x 224 threads (7 warps). Each warp owns ONE private
// tile stage + mbarrier (waiter == refiller: race-free parity), computes a
// whole point (4 rows/thread -> minimal amp broadcast LDS), argmax via pure
// warp shuffles. Points beyond the first 1036 are claimed dynamically from a
// global atomic ticket (kills the static-stride quantization tail); the
// ticket self-resets at kernel end so the graph contains ONE launch.
__global__ __launch_bounds__(THREADS, 1)
void axon_map_kernel(const float* __restrict__ amp,
                     const float* __restrict__ pexp,
                     float* __restrict__ out) {
    extern __shared__ __align__(128) char smem_raw[];
    float* tiles = reinterpret_cast<float*>(smem_raw);              // [NWARPS][7680]
    float* ampt  = tiles + NWARPS * TILE_FLOATS;                    // [NE][NB]
    unsigned long long* mbar =
        reinterpret_cast<unsigned long long*>(ampt + NE * NB);      // [NWARPS]

    const int tid  = threadIdx.x;
    const int warp = tid >> 5;
    const int lane = tid & 31;
    const int bid  = blockIdx.x;

    const uint32_t my_tile_addr =
        (uint32_t)__cvta_generic_to_shared(tiles + warp * TILE_FLOATS);
    const uint32_t my_mbar_addr =
        (uint32_t)__cvta_generic_to_shared(&mbar[warp]);

    if (tid < NWARPS) {
        const uint32_t a = (uint32_t)__cvta_generic_to_shared(&mbar[tid]);
        asm volatile("mbarrier.init.shared.b64 [%0], 1;" :: "r"(a) : "memory");
    }
    for (int i = tid; i < NB * NE; i += THREADS) {
        const int b = i / NE, e = i % NE;
        ampt[e * NB + b] = amp[i];
    }
    __syncthreads();

    const float* tile = tiles + warp * TILE_FLOATS;

    // Prologue: stream s = bid*NWARPS+warp starts on point s (< 1036 < NP).
    int p = bid * NWARPS + warp;
    if (lane == 0)
        tma_fill(my_tile_addr, my_mbar_addr, pexp + (size_t)p * TILE_FLOATS);

    uint32_t parity = 0;
    while (p < NP) {
        mbar_wait(my_mbar_addr, parity);
        parity ^= 1u;

        unsigned long long acc[4][4];   // [row r][batch pair q]
        #pragma unroll
        for (int r = 0; r < 4; r++)
            #pragma unroll
            for (int q = 0; q < 4; q++) acc[r][q] = 0ull;

        #pragma unroll
        for (int j = 0; j < NE / 4; j++) {
            float4 pe[4];
            #pragma unroll
            for (int r = 0; r < 4; r++)
                pe[r] = *reinterpret_cast<const float4*>(tile + (lane + 32 * r) * NE + 4 * j);
            #pragma unroll
            for (int k = 0; k < 4; k++) {
                const int e = 4 * j + k;
                const ulonglong2 alo = *reinterpret_cast<const ulonglong2*>(ampt + e * NB);
                const ulonglong2 ahi = *reinterpret_cast<const ulonglong2*>(ampt + e * NB + 4);
                #pragma unroll
                for (int r = 0; r < 4; r++) {
                    const float pv = (k == 0) ? pe[r].x : (k == 1) ? pe[r].y
                                   : (k == 2) ? pe[r].z : pe[r].w;
                    const unsigned long long d = dup2(pv);
                    fma2(acc[r][0], d, alo.x);
                    fma2(acc[r][1], d, alo.y);
                    fma2(acc[r][2], d, ahi.x);
                    fma2(acc[r][3], d, ahi.y);
                }
            }
        }

        // Claim the next point dynamically and refill own stage for it.
        // Fence orders our generic-proxy tile reads before the async-proxy
        // TMA write; the fill then overlaps the argmax reduction below.
        int pn;
        if (lane == 0) pn = atomicAdd(&g_ticket, 1);
        pn = __shfl_sync(0xffffffffu, pn, 0);
        if (pn < NP) {
            asm volatile("fence.proxy.async.shared::cta;" ::: "memory");
            __syncwarp();
            if (lane == 0)
                tma_fill(my_tile_addr, my_mbar_addr,
                         pexp + (size_t)pn * TILE_FLOATS);
        }

        // abs-argmax over 128 segments per batch: 4-way local, 5-step shuffle.
        #pragma unroll
        for (int b = 0; b < NB; b++) {
            const int q = b >> 1;
            float bv = 0.0f, ba = -1.0f;
            #pragma unroll
            for (int r = 0; r < 4; r++) {
                const unsigned long long pa = acc[r][q];
                const float v = __uint_as_float((b & 1) ? (uint32_t)(pa >> 32) : (uint32_t)pa);
                const float a = fabsf(v);
                if (a > ba) { ba = a; bv = v; }
            }
            #pragma unroll
            for (int off = 16; off > 0; off >>= 1) {
                const float oa = __shfl_xor_sync(0xffffffffu, ba, off);
                const float ov = __shfl_xor_sync(0xffffffffu, bv, off);
                if (oa > ba) { ba = oa; bv = ov; }
            }
            if (lane == 0) out[b * NP + p] = bv;   // threshold |v|>0 is identity
        }

        p = pn;
    }

    // Stream finished. The LAST of the NSTREAMS streams to finish restores
    // the ticket state for the next launch (graph replay). atomicExch gives
    // device-scope visibility; the kernel boundary orders it for launch N+1.
    if (lane == 0) {
        if (atomicAdd(&g_done, 1) == NSTREAMS - 1) {
            atomicExch(&g_ticket, NSTREAMS);
            atomicExch(&g_done, 0);
        }
    }
}

extern "C" void kernel_launch(void* const* d_in, const int* in_sizes, int n_in,
                              void* d_out, int out_size) {
    (void)n_in; (void)out_size;
    const float* a0 = (const float*)d_in[0];
    const float* a1 = (const float*)d_in[1];
    const float* amp  = a0;
    const float* pexp = a1;
    if (in_sizes[0] != NB * NE) { amp = a1; pexp = a0; }

    cudaFuncSetAttribute(axon_map_kernel,
                         cudaFuncAttributeMaxDynamicSharedMemorySize, SMEM_BYTES);
    axon_map_kernel<<<NBLOCKS, THREADS, SMEM_BYTES>>>(amp, pexp, (float*)d_out);
}

// round 15
// speedup vs baseline: 1.0158x; 1.0142x over previous
#include <cuda_runtime.h>
#include <cstdint>

#define NB 8      // batch
#define NP 3249   // grid points
#define NS 128    // axon segments
#define NE 60     // electrodes
#define NWARPS 7
#define THREADS (NWARPS * 32)          // 224
#define NBLOCKS 148
#define TILE_FLOATS (NS * NE)          // 7680
#define TILE_BYTES (TILE_FLOATS * 4)   // 30720
#define NSTREAMS (NBLOCKS * NWARPS)    // 1036 (prologue points 0..1035)

#define SMEM_BYTES (NWARPS * TILE_BYTES + NE * NB * 4 + NWARPS * 8 + 64)

// Work-stealing ticket. Self-resetting: every launch performs exactly NP
// iterations chip-wide and claims one ticket per iteration; the last stream
// to finish restores g_ticket/g_done for the next (graph-replayed) launch.
__device__ int g_ticket = NSTREAMS;
__device__ int g_done = 0;

__device__ __forceinline__ unsigned long long dup2(float x) {
    unsigned long long r;
    asm("mov.b64 %0, {%1, %1};" : "=l"(r) : "f"(x));
    return r;
}
__device__ __forceinline__ void fma2(unsigned long long& d,
                                     unsigned long long a,
                                     unsigned long long b) {
    asm("fma.rn.f32x2 %0, %1, %2, %0;" : "+l"(d) : "l"(a), "l"(b));
}

__device__ __forceinline__ void mbar_wait(uint32_t addr, uint32_t parity) {
    uint32_t done;
    asm volatile("{\n\t.reg .pred p;\n\t"
                 "mbarrier.try_wait.parity.acquire.cta.shared::cta.b64 p, [%1], %2;\n\t"
                 "selp.b32 %0, 1, 0, p;\n\t}"
                 : "=r"(done) : "r"(addr), "r"(parity) : "memory");
    while (!done) {
        asm volatile("{\n\t.reg .pred p;\n\t"
                     "mbarrier.try_wait.parity.acquire.cta.shared::cta.b64 p, [%1], %2, 0x989680;\n\t"
                     "selp.b32 %0, 1, 0, p;\n\t}"
                     : "=r"(done) : "r"(addr), "r"(parity) : "memory");
    }
}

__device__ __forceinline__ void tma_fill(uint32_t tile_addr, uint32_t mbar_addr,
                                         const float* src) {
    asm volatile("mbarrier.arrive.expect_tx.shared.b64 _, [%0], %1;"
                 :: "r"(mbar_addr), "r"((uint32_t)TILE_BYTES) : "memory");
    asm volatile("cp.async.bulk.shared::cluster.global.mbarrier::complete_tx::bytes "
                 "[%0], [%1], %2, [%3];"
                 :: "r"(tile_addr), "l"(src), "r"((uint32_t)TILE_BYTES), "r"(mbar_addr)
                 : "memory");
}

// Persistent: 148 blocks x 224 threads (7 warps). Each warp owns ONE private
// tile stage + mbarrier (waiter == refiller: race-free parity), computes a
// whole point (4 rows/thread -> minimal amp broadcast LDS), argmax via pure
// warp shuffles. Work stealing kills the static-stride tail; NEW: the ticket
// for the NEXT point is claimed at the TOP of the iteration, so the atomic's
// ~320-cycle round trip is hidden behind the mbarrier wait + compute instead
// of delaying the TMA refill (the R12/R14 wall-clock penalty).
__global__ __launch_bounds__(THREADS, 1)
void axon_map_kernel(const float* __restrict__ amp,
                     const float* __restrict__ pexp,
                     float* __restrict__ out) {
    extern __shared__ __align__(128) char smem_raw[];
    float* tiles = reinterpret_cast<float*>(smem_raw);              // [NWARPS][7680]
    float* ampt  = tiles + NWARPS * TILE_FLOATS;                    // [NE][NB]
    unsigned long long* mbar =
        reinterpret_cast<unsigned long long*>(ampt + NE * NB);      // [NWARPS]

    const int tid  = threadIdx.x;
    const int warp = tid >> 5;
    const int lane = tid & 31;
    const int bid  = blockIdx.x;

    const uint32_t my_tile_addr =
        (uint32_t)__cvta_generic_to_shared(tiles + warp * TILE_FLOATS);
    const uint32_t my_mbar_addr =
        (uint32_t)__cvta_generic_to_shared(&mbar[warp]);

    if (tid < NWARPS) {
        const uint32_t a = (uint32_t)__cvta_generic_to_shared(&mbar[tid]);
        asm volatile("mbarrier.init.shared.b64 [%0], 1;" :: "r"(a) : "memory");
    }
    for (int i = tid; i < NB * NE; i += THREADS) {
        const int b = i / NE, e = i % NE;
        ampt[e * NB + b] = amp[i];
    }
    __syncthreads();

    const float* tile = tiles + warp * TILE_FLOATS;

    // Prologue: stream s = bid*NWARPS+warp starts on point s (< 1036 < NP).
    int p = bid * NWARPS + warp;
    if (lane == 0)
        tma_fill(my_tile_addr, my_mbar_addr, pexp + (size_t)p * TILE_FLOATS);

    uint32_t parity = 0;
    while (p < NP) {
        // Claim the NEXT point now: the atomic completes while we wait on the
        // current tile and compute — zero latency exposed at refill time.
        int pn;
        if (lane == 0) pn = atomicAdd(&g_ticket, 1);

        mbar_wait(my_mbar_addr, parity);
        parity ^= 1u;

        unsigned long long acc[4][4];   // [row r][batch pair q]
        #pragma unroll
        for (int r = 0; r < 4; r++)
            #pragma unroll
            for (int q = 0; q < 4; q++) acc[r][q] = 0ull;

        #pragma unroll
        for (int j = 0; j < NE / 4; j++) {
            float4 pe[4];
            #pragma unroll
            for (int r = 0; r < 4; r++)
                pe[r] = *reinterpret_cast<const float4*>(tile + (lane + 32 * r) * NE + 4 * j);
            #pragma unroll
            for (int k = 0; k < 4; k++) {
                const int e = 4 * j + k;
                const ulonglong2 alo = *reinterpret_cast<const ulonglong2*>(ampt + e * NB);
                const ulonglong2 ahi = *reinterpret_cast<const ulonglong2*>(ampt + e * NB + 4);
                #pragma unroll
                for (int r = 0; r < 4; r++) {
                    const float pv = (k == 0) ? pe[r].x : (k == 1) ? pe[r].y
                                   : (k == 2) ? pe[r].z : pe[r].w;
                    const unsigned long long d = dup2(pv);
                    fma2(acc[r][0], d, alo.x);
                    fma2(acc[r][1], d, alo.y);
                    fma2(acc[r][2], d, ahi.x);
                    fma2(acc[r][3], d, ahi.y);
                }
            }
        }

        // Broadcast the pre-claimed ticket and refill immediately. Fence
        // orders our generic-proxy tile reads before the async-proxy TMA
        // write; the fill then overlaps the argmax reduction below.
        pn = __shfl_sync(0xffffffffu, pn, 0);
        if (pn < NP) {
            asm volatile("fence.proxy.async.shared::cta;" ::: "memory");
            __syncwarp();
            if (lane == 0)
                tma_fill(my_tile_addr, my_mbar_addr,
                         pexp + (size_t)pn * TILE_FLOATS);
        }

        // abs-argmax over 128 segments per batch: 4-way local, 5-step shuffle.
        #pragma unroll
        for (int b = 0; b < NB; b++) {
            const int q = b >> 1;
            float bv = 0.0f, ba = -1.0f;
            #pragma unroll
            for (int r = 0; r < 4; r++) {
                const unsigned long long pa = acc[r][q];
                const float v = __uint_as_float((b & 1) ? (uint32_t)(pa >> 32) : (uint32_t)pa);
                const float a = fabsf(v);
                if (a > ba) { ba = a; bv = v; }
            }
            #pragma unroll
            for (int off = 16; off > 0; off >>= 1) {
                const float oa = __shfl_xor_sync(0xffffffffu, ba, off);
                const float ov = __shfl_xor_sync(0xffffffffu, bv, off);
                if (oa > ba) { ba = oa; bv = ov; }
            }
            if (lane == 0) out[b * NP + p] = bv;   // threshold |v|>0 is identity
        }

        p = pn;
    }

    // Stream finished. The LAST of the NSTREAMS streams to finish restores
    // the ticket state for the next launch (graph replay).
    if (lane == 0) {
        if (atomicAdd(&g_done, 1) == NSTREAMS - 1) {
            atomicExch(&g_ticket, NSTREAMS);
            atomicExch(&g_done, 0);
        }
    }
}

extern "C" void kernel_launch(void* const* d_in, const int* in_sizes, int n_in,
                              void* d_out, int out_size) {
    (void)n_in; (void)out_size;
    const float* a0 = (const float*)d_in[0];
    const float* a1 = (const float*)d_in[1];
    const float* amp  = a0;
    const float* pexp = a1;
    if (in_sizes[0] != NB * NE) { amp = a1; pexp = a0; }

    cudaFuncSetAttribute(axon_map_kernel,
                         cudaFuncAttributeMaxDynamicSharedMemorySize, SMEM_BYTES);
    axon_map_kernel<<<NBLOCKS, THREADS, SMEM_BYTES>>>(amp, pexp, (float*)d_out);
}

// round 16
// speedup vs baseline: 1.1263x; 1.1088x over previous
#include <cuda_runtime.h>
#include <cstdint>

#define NB 8      // batch
#define NP 3249   // grid points
#define NS 128    // axon segments
#define NE 60     // electrodes
#define NWARPS 7
#define THREADS (NWARPS * 32)          // 224
#define NBLOCKS 148
#define TILE_FLOATS (NS * NE)          // 7680
#define TILE_BYTES (TILE_FLOATS * 4)   // 30720
#define STRIDE (NBLOCKS * NWARPS)      // 1036

#define SMEM_BYTES (NWARPS * TILE_BYTES + NE * NB * 4 + NWARPS * 8 + 64)

__device__ __forceinline__ unsigned long long dup2(float x) {
    unsigned long long r;
    asm("mov.b64 %0, {%1, %1};" : "=l"(r) : "f"(x));
    return r;
}
__device__ __forceinline__ void fma2(unsigned long long& d,
                                     unsigned long long a,
                                     unsigned long long b) {
    asm("fma.rn.f32x2 %0, %1, %2, %0;" : "+l"(d) : "l"(a), "l"(b));
}

__device__ __forceinline__ void mbar_wait(uint32_t addr, uint32_t parity) {
    uint32_t done;
    asm volatile("{\n\t.reg .pred p;\n\t"
                 "mbarrier.try_wait.parity.acquire.cta.shared::cta.b64 p, [%1], %2;\n\t"
                 "selp.b32 %0, 1, 0, p;\n\t}"
                 : "=r"(done) : "r"(addr), "r"(parity) : "memory");
    while (!done) {
        asm volatile("{\n\t.reg .pred p;\n\t"
                     "mbarrier.try_wait.parity.acquire.cta.shared::cta.b64 p, [%1], %2, 0x989680;\n\t"
                     "selp.b32 %0, 1, 0, p;\n\t}"
                     : "=r"(done) : "r"(addr), "r"(parity) : "memory");
    }
}

// TMA fill with an L2 evict_last cache hint: p_exp is re-read on every graph
// replay and (at 99.8 MB) nearly fits in the 126 MB L2, so biasing the
// replacement policy keeps the tensor resident across launches and services
// fills from L2 instead of DRAM.
__device__ __forceinline__ void tma_fill(uint32_t tile_addr, uint32_t mbar_addr,
                                         const float* src) {
    unsigned long long policy;
    asm volatile("createpolicy.fractional.L2::evict_last.b64 %0, 1.0;"
                 : "=l"(policy));
    asm volatile("mbarrier.arrive.expect_tx.shared.b64 _, [%0], %1;"
                 :: "r"(mbar_addr), "r"((uint32_t)TILE_BYTES) : "memory");
    asm volatile("cp.async.bulk.shared::cluster.global.mbarrier::complete_tx::bytes.L2::cache_hint "
                 "[%0], [%1], %2, [%3], %4;"
                 :: "r"(tile_addr), "l"(src), "r"((uint32_t)TILE_BYTES),
                    "r"(mbar_addr), "l"(policy)
                 : "memory");
}

// Persistent: 148 blocks x 224 threads (7 warps). Each warp owns ONE private
// tile stage + mbarrier (waiter == refiller: race-free parity), computes a
// whole point (4 rows/thread -> minimal amp broadcast LDS), static stride
// (ticket variants measured consistently slower), argmax via pure warp
// shuffles. Single change vs the 18.5us best: evict_last L2 policy on fills.
__global__ __launch_bounds__(THREADS, 1)
void axon_map_kernel(const float* __restrict__ amp,
                     const float* __restrict__ pexp,
                     float* __restrict__ out) {
    extern __shared__ __align__(128) char smem_raw[];
    float* tiles = reinterpret_cast<float*>(smem_raw);              // [NWARPS][7680]
    float* ampt  = tiles + NWARPS * TILE_FLOATS;                    // [NE][NB]
    unsigned long long* mbar =
        reinterpret_cast<unsigned long long*>(ampt + NE * NB);      // [NWARPS]

    const int tid  = threadIdx.x;
    const int warp = tid >> 5;
    const int lane = tid & 31;
    const int bid  = blockIdx.x;

    const uint32_t my_tile_addr =
        (uint32_t)__cvta_generic_to_shared(tiles + warp * TILE_FLOATS);
    const uint32_t my_mbar_addr =
        (uint32_t)__cvta_generic_to_shared(&mbar[warp]);

    if (tid < NWARPS) {
        const uint32_t a = (uint32_t)__cvta_generic_to_shared(&mbar[tid]);
        asm volatile("mbarrier.init.shared.b64 [%0], 1;" :: "r"(a) : "memory");
    }
    for (int i = tid; i < NB * NE; i += THREADS) {
        const int b = i / NE, e = i % NE;
        ampt[e * NB + b] = amp[i];
    }
    __syncthreads();

    const float* tile = tiles + warp * TILE_FLOATS;

    // Prologue: stream s = bid + 148*warp starts on point s (< 1036 < NP).
    const int p0 = bid + NBLOCKS * warp;
    if (lane == 0)
        tma_fill(my_tile_addr, my_mbar_addr, pexp + (size_t)p0 * TILE_FLOATS);

    uint32_t parity = 0;
    for (int p = p0; p < NP; p += STRIDE) {
        mbar_wait(my_mbar_addr, parity);
        parity ^= 1u;

        unsigned long long acc[4][4];   // [row r][batch pair q]
        #pragma unroll
        for (int r = 0; r < 4; r++)
            #pragma unroll
            for (int q = 0; q < 4; q++) acc[r][q] = 0ull;

        #pragma unroll
        for (int j = 0; j < NE / 4; j++) {
            float4 pe[4];
            #pragma unroll
            for (int r = 0; r < 4; r++)
                pe[r] = *reinterpret_cast<const float4*>(tile + (lane + 32 * r) * NE + 4 * j);
            #pragma unroll
            for (int k = 0; k < 4; k++) {
                const int e = 4 * j + k;
                const ulonglong2 alo = *reinterpret_cast<const ulonglong2*>(ampt + e * NB);
                const ulonglong2 ahi = *reinterpret_cast<const ulonglong2*>(ampt + e * NB + 4);
                #pragma unroll
                for (int r = 0; r < 4; r++) {
                    const float pv = (k == 0) ? pe[r].x : (k == 1) ? pe[r].y
                                   : (k == 2) ? pe[r].z : pe[r].w;
                    const unsigned long long d = dup2(pv);
                    fma2(acc[r][0], d, alo.x);
                    fma2(acc[r][1], d, alo.y);
                    fma2(acc[r][2], d, ahi.x);
                    fma2(acc[r][3], d, ahi.y);
                }
            }
        }

        // Refill own stage for the next point. Fence orders our generic-proxy
        // tile reads before the async-proxy TMA write; the fill then overlaps
        // the argmax reduction below.
        const int pn = p + STRIDE;
        if (pn < NP) {
            asm volatile("fence.proxy.async.shared::cta;" ::: "memory");
            __syncwarp();
            if (lane == 0)
                tma_fill(my_tile_addr, my_mbar_addr,
                         pexp + (size_t)pn * TILE_FLOATS);
        }

        // abs-argmax over 128 segments per batch: 4-way local, 5-step shuffle.
        #pragma unroll
        for (int b = 0; b < NB; b++) {
            const int q = b >> 1;
            float bv = 0.0f, ba = -1.0f;
            #pragma unroll
            for (int r = 0; r < 4; r++) {
                const unsigned long long pa = acc[r][q];
                const float v = __uint_as_float((b & 1) ? (uint32_t)(pa >> 32) : (uint32_t)pa);
                const float a = fabsf(v);
                if (a > ba) { ba = a; bv = v; }
            }
            #pragma unroll
            for (int off = 16; off > 0; off >>= 1) {
                const float oa = __shfl_xor_sync(0xffffffffu, ba, off);
                const float ov = __shfl_xor_sync(0xffffffffu, bv, off);
                if (oa > ba) { ba = oa; bv = ov; }
            }
            if (lane == 0) out[b * NP + p] = bv;   // threshold |v|>0 is identity
        }
    }
}

extern "C" void kernel_launch(void* const* d_in, const int* in_sizes, int n_in,
                              void* d_out, int out_size) {
    (void)n_in; (void)out_size;
    const float* a0 = (const float*)d_in[0];
    const float* a1 = (const float*)d_in[1];
    const float* amp  = a0;
    const float* pexp = a1;
    if (in_sizes[0] != NB * NE) { amp = a1; pexp = a0; }

    cudaFuncSetAttribute(axon_map_kernel,
                         cudaFuncAttributeMaxDynamicSharedMemorySize, SMEM_BYTES);
    axon_map_kernel<<<NBLOCKS, THREADS, SMEM_BYTES>>>(amp, pexp, (float*)d_out);
}